// round 15
// baseline (speedup 1.0000x reference)
#include <cuda_runtime.h>
#include <cuda_fp16.h>
#include <math.h>
#include <stdint.h>

#define BDIM 16
#define SEQ  1024
#define HIDN 768
#define NH   12
#define HD   64
#define NBH  (BDIM*NH)   // 192
#define XDP  384          // dpairs per hidden row
#define HDP  32           // dpairs per head row

// Split-fp16 scratch (u32 = half2). Allocation-free: __device__ globals.
__device__ uint32_t g_xh[(size_t)BDIM*SEQ*XDP], g_xl[(size_t)BDIM*SEQ*XDP];
__device__ uint32_t g_wh[(size_t)4*HIDN*XDP],   g_wl[(size_t)4*HIDN*XDP];
__device__ uint32_t g_qh[(size_t)NBH*SEQ*HDP],  g_ql[(size_t)NBH*SEQ*HDP];
__device__ uint32_t g_kh[(size_t)NBH*SEQ*HDP],  g_kl[(size_t)NBH*SEQ*HDP];
__device__ uint32_t g_vth[(size_t)NBH*HD*(SEQ/2)], g_vtl[(size_t)NBH*HD*(SEQ/2)];
__device__ uint32_t g_oh[(size_t)NBH*SEQ*HDP];   // O stored fp16-hi only

__device__ __forceinline__ void mma_f16(float c[4],
    uint32_t a0, uint32_t a1, uint32_t a2, uint32_t a3,
    uint32_t b0, uint32_t b1)
{
    asm volatile(
        "mma.sync.aligned.m16n8k16.row.col.f32.f16.f16.f32 "
        "{%0,%1,%2,%3},{%4,%5,%6,%7},{%8,%9},{%0,%1,%2,%3};\n"
        : "+f"(c[0]), "+f"(c[1]), "+f"(c[2]), "+f"(c[3])
        : "r"(a0), "r"(a1), "r"(a2), "r"(a3), "r"(b0), "r"(b1));
}

__device__ __forceinline__ void ldsm4(uint32_t &r0, uint32_t &r1,
                                      uint32_t &r2, uint32_t &r3, uint32_t a){
    asm volatile("ldmatrix.sync.aligned.m8n8.x4.shared.b16 {%0,%1,%2,%3}, [%4];"
        : "=r"(r0), "=r"(r1), "=r"(r2), "=r"(r3) : "r"(a));
}

__device__ __forceinline__ uint32_t packh(__half a, __half b){
    __half2 h = __halves2half2(a, b);
    return *(uint32_t*)&h;
}
__device__ __forceinline__ void split_pair(float x, float y, uint32_t &hi, uint32_t &lo){
    __half hx = __float2half_rn(x);
    __half hy = __float2half_rn(y);
    __half lx = __float2half_rn(x - __half2float(hx));
    __half ly = __float2half_rn(y - __half2float(hy));
    hi = packh(hx, hy);
    lo = packh(lx, ly);
}

__device__ __forceinline__ uint32_t smaddr(const void* p){
    return (uint32_t)__cvta_generic_to_shared(p);
}
__device__ __forceinline__ void cp16(uint32_t s, const void* g){
    asm volatile("cp.async.cg.shared.global [%0], [%1], 16;\n" :: "r"(s), "l"(g));
}
__device__ __forceinline__ void cp_commit(){
    asm volatile("cp.async.commit_group;\n" ::: "memory");
}
__device__ __forceinline__ void cp_wait1(){
    asm volatile("cp.async.wait_group 1;\n" ::: "memory");
}
__device__ __forceinline__ void cp_wait0(){
    asm volatile("cp.async.wait_group 0;\n" ::: "memory");
}

#define KS 36   // stride for 32-dpair rows; (4r+c)%32 bank permutation

// ---------------------------------------------------------------------------
// Split conversions.
// ---------------------------------------------------------------------------
__global__ __launch_bounds__(256) void split_conv_x(const float* __restrict__ src,
                                                    int nf4)
{
    int i = blockIdx.x*blockDim.x + threadIdx.x;
    if (i >= nf4) return;
    float4 v = ((const float4*)src)[i];
    uint32_t h0,l0,h1,l1;
    split_pair(v.x, v.y, h0, l0);
    split_pair(v.z, v.w, h1, l1);
    g_xh[2*i  ] = h0; g_xh[2*i+1] = h1;
    g_xl[2*i  ] = l0; g_xl[2*i+1] = l1;
}

__global__ __launch_bounds__(256) void split_conv_w(
    const float* __restrict__ Wq, const float* __restrict__ Wk,
    const float* __restrict__ Wv, const float* __restrict__ Wo, int nf4)
{
    int i = blockIdx.x*blockDim.x + threadIdx.x;
    if (i >= nf4) return;
    int which = blockIdx.y;
    const float* src = (which==0)?Wq:(which==1)?Wk:(which==2)?Wv:Wo;
    size_t off = (size_t)which*HIDN*XDP;
    float4 v = ((const float4*)src)[i];
    uint32_t h0,l0,h1,l1;
    split_pair(v.x, v.y, h0, l0);
    split_pair(v.z, v.w, h1, l1);
    g_wh[off + 2*i  ] = h0; g_wh[off + 2*i+1] = h1;
    g_wl[off + 2*i  ] = l0; g_wl[off + 2*i+1] = l1;
}

// ---------------------------------------------------------------------------
// Fused QKV projection. grid=(64,12,3), 512 thr. BM=256, BN=64, BK=32dp,
// 2-stage cp.async double buffer, ldmatrix loads. 16 warps as 8(m)x2(n).
// z==2 (V): 2-term split, and the epilogue transposes V in SMEM (stage
// buffers are dead) writing g_vt directly -- no separate vtrans kernel.
// ---------------------------------------------------------------------------
#define GSTAGE    (256*KS + 256*KS + 64*KS + 64*KS)   // 23040 u32
#define GEMM_SMEM (GSTAGE*2*4)                        // 184320 B
#define GEMM_NK   (XDP/32)                            // 12

__global__ __launch_bounds__(512) void qkv_kernel(
    const float* __restrict__ bq, const float* __restrict__ bk,
    const float* __restrict__ bv,
    const float* __restrict__ cosc, const float* __restrict__ sinc)
{
    extern __shared__ uint32_t smem[];

    const int z    = blockIdx.z;
    const int h    = blockIdx.y;
    const int row0 = blockIdx.x * 256;
    const int tid  = threadIdx.x;
    const int w    = tid >> 5, lane = tid & 31;
    const int g    = lane >> 2, q = lane & 3;
    const int warpm = w >> 1, warpn = w & 1;     // 8 x 2
    const bool three_term = (z != 2);

    const uint32_t* wbh = g_wh + (size_t)z*HIDN*XDP + (size_t)h*64*XDP;
    const uint32_t* wbl = g_wl + (size_t)z*HIDN*XDP + (size_t)h*64*XDP;
    const float* bias = (z==0) ? bq : (z==1) ? bk : bv;
    uint32_t* ohp = (z==0) ? g_qh : g_kh;
    uint32_t* olp = (z==0) ? g_ql : g_kl;
    const float sc = (z==0) ? 0.125f : 1.0f;

    float c[2][4][4];
    #pragma unroll
    for (int mf=0; mf<2; mf++)
        #pragma unroll
        for (int nf=0; nf<4; nf++)
            #pragma unroll
            for (int e=0; e<4; e++) c[mf][nf][e]=0.f;

    const int lrow = tid >> 3;            // 0..63
    const int koff = (tid & 7) * 4;       // 0..28 u32

    const int rr  = lane & 7;
    const int a_row = rr + ((lane>>3)&1)*8;
    const int a_col = (lane>>4)*4;
    const int b_tt4 = (lane>>3)*4;

    auto load_stage = [&](int it, int st){
        uint32_t* base = smem + st*GSTAGE;
        uint32_t* xh = base;
        uint32_t* xl = base + 256*KS;
        uint32_t* wh = base + 512*KS;
        uint32_t* wl = base + 512*KS + 64*KS;
        int k0 = it*32;
        #pragma unroll
        for (int i=0; i<4; i++){
            int r = lrow + 64*i;
            cp16(smaddr(&xh[r*KS + koff]), g_xh + (size_t)(row0+r)*XDP + k0 + koff);
            if (three_term)
                cp16(smaddr(&xl[r*KS + koff]), g_xl + (size_t)(row0+r)*XDP + k0 + koff);
        }
        if (lrow < 64){
            cp16(smaddr(&wh[lrow*KS + koff]), wbh + (size_t)lrow*XDP + k0 + koff);
            cp16(smaddr(&wl[lrow*KS + koff]), wbl + (size_t)lrow*XDP + k0 + koff);
        }
        cp_commit();
    };

    load_stage(0, 0);
    for (int it=0; it<GEMM_NK; it++){
        int cur = it & 1;
        if (it+1 < GEMM_NK) load_stage(it+1, cur^1);
        if (it+1 < GEMM_NK) cp_wait1(); else cp_wait0();
        __syncthreads();
        uint32_t* base = smem + cur*GSTAGE;
        uint32_t* xh = base;
        uint32_t* xl = base + 256*KS;
        uint32_t* wh = base + 512*KS;
        uint32_t* wl = base + 512*KS + 64*KS;
        #pragma unroll
        for (int kfp=0; kfp<2; kfp++){
            uint32_t ah[2][2][4], al[2][2][4];
            #pragma unroll
            for (int kk=0; kk<2; kk++){
                int kf = 2*kfp + kk;
                #pragma unroll
                for (int mf=0; mf<2; mf++){
                    int r = warpm*32 + mf*16 + a_row;
                    ldsm4(ah[kk][mf][0],ah[kk][mf][1],ah[kk][mf][2],ah[kk][mf][3],
                          smaddr(&xh[r*KS + kf*8 + a_col]));
                    if (three_term)
                        ldsm4(al[kk][mf][0],al[kk][mf][1],al[kk][mf][2],al[kk][mf][3],
                              smaddr(&xl[r*KS + kf*8 + a_col]));
                }
            }
            #pragma unroll
            for (int nf=0; nf<4; nf++){
                int n = warpn*32 + nf*8 + rr;
                uint32_t bh0,bh1,bh2,bh3, bl0,bl1,bl2,bl3;
                ldsm4(bh0,bh1,bh2,bh3, smaddr(&wh[n*KS + kfp*16 + b_tt4]));
                ldsm4(bl0,bl1,bl2,bl3, smaddr(&wl[n*KS + kfp*16 + b_tt4]));
                #pragma unroll
                for (int mf=0; mf<2; mf++){
                    mma_f16(c[mf][nf], ah[0][mf][0],ah[0][mf][1],ah[0][mf][2],ah[0][mf][3], bh0,bh1);
                    mma_f16(c[mf][nf], ah[0][mf][0],ah[0][mf][1],ah[0][mf][2],ah[0][mf][3], bl0,bl1);
                    if (three_term)
                        mma_f16(c[mf][nf], al[0][mf][0],al[0][mf][1],al[0][mf][2],al[0][mf][3], bh0,bh1);
                    mma_f16(c[mf][nf], ah[1][mf][0],ah[1][mf][1],ah[1][mf][2],ah[1][mf][3], bh2,bh3);
                    mma_f16(c[mf][nf], ah[1][mf][0],ah[1][mf][1],ah[1][mf][2],ah[1][mf][3], bl2,bl3);
                    if (three_term)
                        mma_f16(c[mf][nf], al[1][mf][0],al[1][mf][1],al[1][mf][2],al[1][mf][3], bh2,bh3);
                }
            }
        }
        __syncthreads();
    }

    if (z != 2){
        // Q/K epilogue: bias + RoPE + scale, split-u32 global stores.
        #pragma unroll
        for (int nf=0; nf<4; nf++){
            int col = warpn*32 + nf*8 + 2*q;
            float b0 = bias[h*64 + col], b1 = bias[h*64 + col + 1];
            int t = col >> 1;
            #pragma unroll
            for (int mf=0; mf<2; mf++){
                #pragma unroll
                for (int half=0; half<2; half++){
                    int row = row0 + warpm*32 + mf*16 + g + half*8;
                    int b_ = row >> 10, s_ = row & 1023;
                    float v0 = c[mf][nf][half*2+0] + b0;
                    float v1 = c[mf][nf][half*2+1] + b1;
                    float cs_ = cosc[s_*32 + t], sn_ = sinc[s_*32 + t];
                    float r0v = (v0*cs_ - v1*sn_)*sc;
                    float r1v = (v1*cs_ + v0*sn_)*sc;
                    uint32_t hi, lo;
                    split_pair(r0v, r1v, hi, lo);
                    size_t idx = ((size_t)(b_*NH + h)*SEQ + s_)*HDP + t;
                    ohp[idx] = hi; olp[idx] = lo;
                }
            }
        }
    } else {
        // V epilogue: bias + split into SMEM vbuf [key][dp], then in-SMEM
        // transpose (byte_perm) writing g_vt[d][keypair] directly.
        uint32_t* vbh = smem;                // 256*KS
        uint32_t* vbl = smem + 256*KS;
        #pragma unroll
        for (int nf=0; nf<4; nf++){
            int col = warpn*32 + nf*8 + 2*q;
            float b0 = bias[h*64 + col], b1 = bias[h*64 + col + 1];
            int t = col >> 1;
            #pragma unroll
            for (int mf=0; mf<2; mf++){
                #pragma unroll
                for (int half=0; half<2; half++){
                    int rowl = warpm*32 + mf*16 + g + half*8;
                    float v0 = c[mf][nf][half*2+0] + b0;
                    float v1 = c[mf][nf][half*2+1] + b1;
                    uint32_t hi, lo;
                    split_pair(v0, v1, hi, lo);
                    vbh[rowl*KS + t] = hi;
                    vbl[rowl*KS + t] = lo;
                }
            }
        }
        __syncthreads();

        const int d    = tid & 63;       // broadcast-friendly map
        const int kgrp = tid >> 6;       // 0..7, 16 keypairs each
        const int dp   = d >> 1;
        const uint32_t sel = (d & 1) ? 0x7632u : 0x5410u;
        const int b_ = row0 >> 10, s0 = row0 & 1023;
        const int bh = b_*NH + h;
        uint32_t outh[16], outl[16];
        #pragma unroll
        for (int j=0; j<16; j++){
            int lk = kgrp*16 + j;        // local keypair 0..127
            outh[j] = __byte_perm(vbh[(2*lk)*KS + dp], vbh[(2*lk+1)*KS + dp], sel);
            outl[j] = __byte_perm(vbl[(2*lk)*KS + dp], vbl[(2*lk+1)*KS + dp], sel);
        }
        uint32_t* dsth = g_vth + ((size_t)bh*HD + d)*(SEQ/2) + s0/2 + kgrp*16;
        uint32_t* dstl = g_vtl + ((size_t)bh*HD + d)*(SEQ/2) + s0/2 + kgrp*16;
        #pragma unroll
        for (int j=0; j<16; j+=4){
            *(uint4*)(dsth + j) = make_uint4(outh[j],outh[j+1],outh[j+2],outh[j+3]);
            *(uint4*)(dstl + j) = make_uint4(outl[j],outl[j+1],outl[j+2],outl[j+3]);
        }
    }
}

// ---------------------------------------------------------------------------
// RSE attention. CTA = 128 query rows of one (b,h), 8 warps. QK^T 3-term;
// PV w_hi-only with w in registers. ldmatrix B-operand loads.
// ---------------------------------------------------------------------------
#define KV_STAGE  (4*64*KS)                         // 9216 u32
#define ATTN_SMEM ((KV_STAGE*2)*4)                  // 73728 B

__global__ __launch_bounds__(256) void attn_kernel(const float* __restrict__ lam_p)
{
    extern __shared__ uint32_t smem[];

    const int bh = blockIdx.y;
    const int m0 = blockIdx.x * 128;
    const int tid = threadIdx.x;
    const int w = tid >> 5, lane = tid & 31;
    const int g = lane >> 2, q = lane & 3;
    const float lam = *lam_p;

    uint32_t qah[4][4], qal[4][4];
    {
        const uint32_t* ph = g_qh + ((size_t)bh*SEQ + m0 + 16*w)*HDP;
        const uint32_t* pl = g_ql + ((size_t)bh*SEQ + m0 + 16*w)*HDP;
        #pragma unroll
        for (int kf=0; kf<4; kf++){
            qah[kf][0] = ph[(size_t)(g  )*HDP + kf*8 + q  ];
            qah[kf][1] = ph[(size_t)(g+8)*HDP + kf*8 + q  ];
            qah[kf][2] = ph[(size_t)(g  )*HDP + kf*8 + q+4];
            qah[kf][3] = ph[(size_t)(g+8)*HDP + kf*8 + q+4];
            qal[kf][0] = pl[(size_t)(g  )*HDP + kf*8 + q  ];
            qal[kf][1] = pl[(size_t)(g+8)*HDP + kf*8 + q  ];
            qal[kf][2] = pl[(size_t)(g  )*HDP + kf*8 + q+4];
            qal[kf][3] = pl[(size_t)(g+8)*HDP + kf*8 + q+4];
        }
    }

    float rem0=1.f, rem1=1.f, li0=0.f, li1=0.f, mi0=-INFINITY, mi1=-INFINITY;
    float acc[8][4];
    #pragma unroll
    for (int nf=0; nf<8; nf++)
        #pragma unroll
        for (int e=0; e<4; e++) acc[nf][e]=0.f;

    const float sq0 = (float)(m0 + 16*w + g);
    const float sq1 = sq0 + 8.f;

    const int lrow = tid >> 3;
    const int koff = (tid & 7) * 4;
    const int rr   = lane & 7;
    const int tt4  = (lane >> 3) * 4;

    auto load_tile = [&](int nb2, int st){
        uint32_t* base = smem + st*KV_STAGE;
        uint32_t* kh  = base;
        uint32_t* kl  = base + 64*KS;
        uint32_t* vth = base + 128*KS;
        uint32_t* vtl = base + 192*KS;
        const uint32_t* kph = g_kh + ((size_t)bh*SEQ + nb2*64)*HDP;
        const uint32_t* kpl = g_kl + ((size_t)bh*SEQ + nb2*64)*HDP;
        const uint32_t* vph = g_vth + (size_t)bh*HD*(SEQ/2) + nb2*32;
        const uint32_t* vpl = g_vtl + (size_t)bh*HD*(SEQ/2) + nb2*32;
        #pragma unroll
        for (int i=0; i<2; i++){
            int r = lrow + 32*i;
            cp16(smaddr(&kh[r*KS + koff]),  kph + (size_t)r*HDP + koff);
            cp16(smaddr(&kl[r*KS + koff]),  kpl + (size_t)r*HDP + koff);
            cp16(smaddr(&vth[r*KS + koff]), vph + (size_t)r*(SEQ/2) + koff);
            cp16(smaddr(&vtl[r*KS + koff]), vpl + (size_t)r*(SEQ/2) + koff);
        }
        cp_commit();
    };

    load_tile(0, 0);
    for (int nb2=0; nb2<16; nb2++){
        int cur = nb2 & 1;
        if (nb2+1 < 16) load_tile(nb2+1, cur^1);
        if (nb2+1 < 16) cp_wait1(); else cp_wait0();
        __syncthreads();
        uint32_t* base = smem + cur*KV_STAGE;
        uint32_t* kh  = base;
        uint32_t* kl  = base + 64*KS;
        uint32_t* vth = base + 128*KS;
        uint32_t* vtl = base + 192*KS;

        #pragma unroll
        for (int sub=0; sub<2; sub++){
            const int nb = nb2*2 + sub;

            float cf[4][4];
            #pragma unroll
            for (int nf=0; nf<4; nf++){
                #pragma unroll
                for (int e=0; e<4; e++) cf[nf][e]=0.f;
                int n = sub*32 + nf*8 + rr;
                #pragma unroll
                for (int kfp=0; kfp<2; kfp++){
                    uint32_t bh0,bh1,bh2,bh3, bl0,bl1,bl2,bl3;
                    ldsm4(bh0,bh1,bh2,bh3, smaddr(&kh[n*KS + kfp*16 + tt4]));
                    ldsm4(bl0,bl1,bl2,bl3, smaddr(&kl[n*KS + kfp*16 + tt4]));
                    int kf0 = 2*kfp, kf1 = 2*kfp+1;
                    mma_f16(cf[nf], qah[kf0][0],qah[kf0][1],qah[kf0][2],qah[kf0][3], bh0,bh1);
                    mma_f16(cf[nf], qah[kf0][0],qah[kf0][1],qah[kf0][2],qah[kf0][3], bl0,bl1);
                    mma_f16(cf[nf], qal[kf0][0],qal[kf0][1],qal[kf0][2],qal[kf0][3], bh0,bh1);
                    mma_f16(cf[nf], qah[kf1][0],qah[kf1][1],qah[kf1][2],qah[kf1][3], bh2,bh3);
                    mma_f16(cf[nf], qah[kf1][0],qah[kf1][1],qah[kf1][2],qah[kf1][3], bl2,bl3);
                    mma_f16(cf[nf], qal[kf1][0],qal[kf1][1],qal[kf1][2],qal[kf1][3], bh2,bh3);
                }
            }

            uint32_t wa0[4], wa1[4];
            float sw0=0.f, sw1=0.f, mx0=-INFINITY, mx1=-INFINITY;
            #pragma unroll
            for (int nf=0; nf<4; nf++){
                int colk = nf*8 + 2*q;
                float sk0 = (float)(nb*32 + colk);
                float sk1 = sk0 + 1.f;
                {
                    float raw0 = cf[nf][0] - lam*fabsf(sq0 - sk0);
                    float raw1 = cf[nf][1] - lam*fabsf(sq0 - sk1);
                    mx0 = fmaxf(mx0, fmaxf(raw0, raw1));
                    float cl0 = fminf(fmaxf(raw0, -20.f), 20.f);
                    float cl1 = fminf(fmaxf(raw1, -20.f), 20.f);
                    float w0 = __fdividef(rem0, 1.f + __expf(-cl0));
                    float w1 = __fdividef(rem0, 1.f + __expf(-cl1));
                    sw0 += w0 + w1;
                    wa0[nf] = packh(__float2half_rn(w0), __float2half_rn(w1));
                }
                {
                    float raw0 = cf[nf][2] - lam*fabsf(sq1 - sk0);
                    float raw1 = cf[nf][3] - lam*fabsf(sq1 - sk1);
                    mx1 = fmaxf(mx1, fmaxf(raw0, raw1));
                    float cl0 = fminf(fmaxf(raw0, -20.f), 20.f);
                    float cl1 = fminf(fmaxf(raw1, -20.f), 20.f);
                    float w0 = __fdividef(rem1, 1.f + __expf(-cl0));
                    float w1 = __fdividef(rem1, 1.f + __expf(-cl1));
                    sw1 += w0 + w1;
                    wa1[nf] = packh(__float2half_rn(w0), __float2half_rn(w1));
                }
            }
            #pragma unroll
            for (int ofs=2; ofs>0; ofs>>=1){
                sw0 += __shfl_xor_sync(0xffffffffu, sw0, ofs);
                sw1 += __shfl_xor_sync(0xffffffffu, sw1, ofs);
                mx0  = fmaxf(mx0, __shfl_xor_sync(0xffffffffu, mx0, ofs));
                mx1  = fmaxf(mx1, __shfl_xor_sync(0xffffffffu, mx1, ofs));
            }
            {
                float mn = fmaxf(mi0, mx0);
                li0 = li0*exp2f(mi0-mn) + sw0; mi0 = mn;
                rem0 = fmaxf(rem0*(1.f - sw0), 1e-6f);
            }
            {
                float mn = fmaxf(mi1, mx1);
                li1 = li1*exp2f(mi1-mn) + sw1; mi1 = mn;
                rem1 = fmaxf(rem1*(1.f - sw1), 1e-6f);
            }

            #pragma unroll
            for (int nf=0; nf<8; nf++){
                int n = nf*8 + rr;
                uint32_t vh0,vh1,vh2,vh3, vl0,vl1,vl2,vl3;
                ldsm4(vh0,vh1,vh2,vh3, smaddr(&vth[n*KS + sub*16 + tt4]));
                ldsm4(vl0,vl1,vl2,vl3, smaddr(&vtl[n*KS + sub*16 + tt4]));
                mma_f16(acc[nf], wa0[0],wa1[0],wa0[1],wa1[1], vh0,vh1);
                mma_f16(acc[nf], wa0[0],wa1[0],wa0[1],wa1[1], vl0,vl1);
                mma_f16(acc[nf], wa0[2],wa1[2],wa0[3],wa1[3], vh2,vh3);
                mma_f16(acc[nf], wa0[2],wa1[2],wa0[3],wa1[3], vl2,vl3);
            }
        }
        __syncthreads();
    }

    const float inv0 = __fdividef(1.f, fmaxf(li0, 1e-6f));
    const float inv1 = __fdividef(1.f, fmaxf(li1, 1e-6f));
    uint32_t* poh = g_oh + ((size_t)bh*SEQ + m0 + 16*w)*HDP;
    #pragma unroll
    for (int nf=0; nf<8; nf++){
        int dp = nf*4 + q;
        poh[(size_t)(g  )*HDP + dp] =
            packh(__float2half_rn(acc[nf][0]*inv0), __float2half_rn(acc[nf][1]*inv0));
        poh[(size_t)(g+8)*HDP + dp] =
            packh(__float2half_rn(acc[nf][2]*inv1), __float2half_rn(acc[nf][3]*inv1));
    }
}

// ---------------------------------------------------------------------------
// Output projection: y = O_hi @ (Wo_hi + Wo_lo)^T + bo. grid=(128,12).
// BM=128, BN=64, BK=32dp, 2-stage cp.async, ldmatrix fragment loads.
// ---------------------------------------------------------------------------
#define OSTAGE   (128*KS + 64*KS + 64*KS)   // 9216 u32
#define OUT_SMEM (OSTAGE*2*4)               // 73728 B

__global__ __launch_bounds__(256) void out_kernel(
    const float* __restrict__ bo, float* __restrict__ y)
{
    extern __shared__ uint32_t smem[];

    const int row0 = blockIdx.x * 128;
    const int cb   = blockIdx.y;
    const int tid  = threadIdx.x;
    const int w    = tid >> 5, lane = tid & 31;
    const int g    = lane >> 2, q = lane & 3;
    const int warpm = w >> 1, warpn = w & 1;

    float c[2][4][4];
    #pragma unroll
    for (int mf=0; mf<2; mf++)
        #pragma unroll
        for (int nf=0; nf<4; nf++)
            #pragma unroll
            for (int e=0; e<4; e++) c[mf][nf][e]=0.f;

    const int lrow = tid >> 3;
    const int koff = (tid & 7) * 4;
    const int rr  = lane & 7;
    const int a_row = rr + ((lane>>3)&1)*8;
    const int a_col = (lane>>4)*4;
    const int b_tt4 = (lane>>3)*4;
    const uint32_t* wbh = g_wh + (size_t)(3*HIDN + cb*64)*XDP;
    const uint32_t* wbl = g_wl + (size_t)(3*HIDN + cb*64)*XDP;

    auto load_stage = [&](int it, int st){
        uint32_t* base = smem + st*OSTAGE;
        uint32_t* xh = base;
        uint32_t* wh = base + 128*KS;
        uint32_t* wl = base + 128*KS + 64*KS;
        int k0 = it*32;
        const int hh = it;               // BK = one head
        #pragma unroll
        for (int i=0; i<4; i++){
            int r = lrow + 32*i;
            int grow = row0 + r;
            int b_ = grow >> 10, s_ = grow & 1023;
            size_t xi = ((size_t)(b_*NH + hh)*SEQ + s_)*HDP + koff;
            cp16(smaddr(&xh[r*KS + koff]), g_oh + xi);
        }
        #pragma unroll
        for (int i=0; i<2; i++){
            int r = lrow + 32*i;
            cp16(smaddr(&wh[r*KS + koff]), wbh + (size_t)r*XDP + k0 + koff);
            cp16(smaddr(&wl[r*KS + koff]), wbl + (size_t)r*XDP + k0 + koff);
        }
        cp_commit();
    };

    load_stage(0, 0);
    for (int it=0; it<GEMM_NK; it++){
        int cur = it & 1;
        if (it+1 < GEMM_NK) load_stage(it+1, cur^1);
        if (it+1 < GEMM_NK) cp_wait1(); else cp_wait0();
        __syncthreads();
        uint32_t* base = smem + cur*OSTAGE;
        uint32_t* xh = base;
        uint32_t* wh = base + 128*KS;
        uint32_t* wl = base + 128*KS + 64*KS;
        #pragma unroll
        for (int kfp=0; kfp<2; kfp++){
            uint32_t ah[2][2][4];
            #pragma unroll
            for (int kk=0; kk<2; kk++){
                int kf = 2*kfp + kk;
                #pragma unroll
                for (int mf=0; mf<2; mf++){
                    int r = warpm*32 + mf*16 + a_row;
                    ldsm4(ah[kk][mf][0],ah[kk][mf][1],ah[kk][mf][2],ah[kk][mf][3],
                          smaddr(&xh[r*KS + kf*8 + a_col]));
                }
            }
            #pragma unroll
            for (int nf=0; nf<4; nf++){
                int n = warpn*32 + nf*8 + rr;
                uint32_t bh0,bh1,bh2,bh3, bl0,bl1,bl2,bl3;
                ldsm4(bh0,bh1,bh2,bh3, smaddr(&wh[n*KS + kfp*16 + b_tt4]));
                ldsm4(bl0,bl1,bl2,bl3, smaddr(&wl[n*KS + kfp*16 + b_tt4]));
                #pragma unroll
                for (int mf=0; mf<2; mf++){
                    mma_f16(c[mf][nf], ah[0][mf][0],ah[0][mf][1],ah[0][mf][2],ah[0][mf][3], bh0,bh1);
                    mma_f16(c[mf][nf], ah[0][mf][0],ah[0][mf][1],ah[0][mf][2],ah[0][mf][3], bl0,bl1);
                    mma_f16(c[mf][nf], ah[1][mf][0],ah[1][mf][1],ah[1][mf][2],ah[1][mf][3], bh2,bh3);
                    mma_f16(c[mf][nf], ah[1][mf][0],ah[1][mf][1],ah[1][mf][2],ah[1][mf][3], bl2,bl3);
                }
            }
        }
        __syncthreads();
    }

    #pragma unroll
    for (int nf=0; nf<4; nf++){
        int col = cb*64 + warpn*32 + nf*8 + 2*q;
        float b0 = bo[col], b1 = bo[col+1];
        #pragma unroll
        for (int mf=0; mf<2; mf++){
            #pragma unroll
            for (int half=0; half<2; half++){
                int row = row0 + warpm*32 + mf*16 + g + half*8;
                *(float2*)(y + (size_t)row*HIDN + col) =
                    make_float2(c[mf][nf][half*2+0] + b0,
                                c[mf][nf][half*2+1] + b1);
            }
        }
    }
}

// ---------------------------------------------------------------------------
extern "C" void kernel_launch(void* const* d_in, const int* in_sizes, int n_in,
                              void* d_out, int out_size)
{
    const float* x    = (const float*)d_in[0];
    const float* Wq   = (const float*)d_in[1];
    const float* bq   = (const float*)d_in[2];
    const float* Wk   = (const float*)d_in[3];
    const float* bk   = (const float*)d_in[4];
    const float* Wv   = (const float*)d_in[5];
    const float* bv   = (const float*)d_in[6];
    const float* Wo   = (const float*)d_in[7];
    const float* bo   = (const float*)d_in[8];
    const float* lam  = (const float*)d_in[9];
    const float* cosc = (const float*)d_in[10];
    const float* sinc = (const float*)d_in[11];
    float* y = (float*)d_out;

    static int configured = 0;
    if (!configured){
        cudaFuncSetAttribute(qkv_kernel,  cudaFuncAttributeMaxDynamicSharedMemorySize, GEMM_SMEM);
        cudaFuncSetAttribute(attn_kernel, cudaFuncAttributeMaxDynamicSharedMemorySize, ATTN_SMEM);
        cudaFuncSetAttribute(out_kernel,  cudaFuncAttributeMaxDynamicSharedMemorySize, OUT_SMEM);
        configured = 1;
    }

    const int nf4_x = BDIM*SEQ*HIDN/4;
    const int nf4_w = HIDN*HIDN/4;
    split_conv_x<<<(nf4_x+255)/256, 256>>>(x, nf4_x);
    dim3 gw((nf4_w+255)/256, 4);
    split_conv_w<<<gw, 256>>>(Wq, Wk, Wv, Wo, nf4_w);

    dim3 g1(BDIM*SEQ/256, NH, 3);
    qkv_kernel<<<g1, 512, GEMM_SMEM>>>(bq, bk, bv, cosc, sinc);

    dim3 g2(SEQ/128, NBH);
    attn_kernel<<<g2, 256, ATTN_SMEM>>>(lam);

    dim3 g3(BDIM*SEQ/128, NH);
    out_kernel<<<g3, 256, OUT_SMEM>>>(bo, y);
}

// round 16
// speedup vs baseline: 1.0989x; 1.0989x over previous
#include <cuda_runtime.h>
#include <cuda_fp16.h>
#include <math.h>
#include <stdint.h>

#define BDIM 16
#define SEQ  1024
#define HIDN 768
#define NH   12
#define HD   64
#define NBH  (BDIM*NH)   // 192
#define XDP  384          // dpairs per hidden row
#define HDP  32           // dpairs per head row

// Split-fp16 scratch (u32 = half2). Allocation-free: __device__ globals.
__device__ uint32_t g_xh[(size_t)BDIM*SEQ*XDP], g_xl[(size_t)BDIM*SEQ*XDP];
__device__ uint32_t g_wh[(size_t)4*HIDN*XDP],   g_wl[(size_t)4*HIDN*XDP];
__device__ uint32_t g_qh[(size_t)NBH*SEQ*HDP],  g_ql[(size_t)NBH*SEQ*HDP];
__device__ uint32_t g_kh[(size_t)NBH*SEQ*HDP],  g_kl[(size_t)NBH*SEQ*HDP];
__device__ uint32_t g_vth[(size_t)NBH*HD*(SEQ/2)], g_vtl[(size_t)NBH*HD*(SEQ/2)];
__device__ uint32_t g_oh[(size_t)NBH*SEQ*HDP];   // O stored fp16-hi only

__device__ __forceinline__ void mma_f16(float c[4],
    uint32_t a0, uint32_t a1, uint32_t a2, uint32_t a3,
    uint32_t b0, uint32_t b1)
{
    asm volatile(
        "mma.sync.aligned.m16n8k16.row.col.f32.f16.f16.f32 "
        "{%0,%1,%2,%3},{%4,%5,%6,%7},{%8,%9},{%0,%1,%2,%3};\n"
        : "+f"(c[0]), "+f"(c[1]), "+f"(c[2]), "+f"(c[3])
        : "r"(a0), "r"(a1), "r"(a2), "r"(a3), "r"(b0), "r"(b1));
}

__device__ __forceinline__ void ldsm4(uint32_t &r0, uint32_t &r1,
                                      uint32_t &r2, uint32_t &r3, uint32_t a){
    asm volatile("ldmatrix.sync.aligned.m8n8.x4.shared.b16 {%0,%1,%2,%3}, [%4];"
        : "=r"(r0), "=r"(r1), "=r"(r2), "=r"(r3) : "r"(a));
}

__device__ __forceinline__ uint32_t packh(__half a, __half b){
    __half2 h = __halves2half2(a, b);
    return *(uint32_t*)&h;
}
__device__ __forceinline__ void split_pair(float x, float y, uint32_t &hi, uint32_t &lo){
    __half hx = __float2half_rn(x);
    __half hy = __float2half_rn(y);
    __half lx = __float2half_rn(x - __half2float(hx));
    __half ly = __float2half_rn(y - __half2float(hy));
    hi = packh(hx, hy);
    lo = packh(lx, ly);
}

__device__ __forceinline__ uint32_t smaddr(const void* p){
    return (uint32_t)__cvta_generic_to_shared(p);
}
__device__ __forceinline__ void cp16(uint32_t s, const void* g){
    asm volatile("cp.async.cg.shared.global [%0], [%1], 16;\n" :: "r"(s), "l"(g));
}
__device__ __forceinline__ void cp_commit(){
    asm volatile("cp.async.commit_group;\n" ::: "memory");
}
__device__ __forceinline__ void cp_wait1(){
    asm volatile("cp.async.wait_group 1;\n" ::: "memory");
}
__device__ __forceinline__ void cp_wait0(){
    asm volatile("cp.async.wait_group 0;\n" ::: "memory");
}

#define KS 36   // stride for 32-dpair rows; (4r+c)%32 bank permutation

// ---------------------------------------------------------------------------
// Split conversions.
// ---------------------------------------------------------------------------
__global__ __launch_bounds__(256) void split_conv_x(const float* __restrict__ src,
                                                    int nf4)
{
    int i = blockIdx.x*blockDim.x + threadIdx.x;
    if (i >= nf4) return;
    float4 v = ((const float4*)src)[i];
    uint32_t h0,l0,h1,l1;
    split_pair(v.x, v.y, h0, l0);
    split_pair(v.z, v.w, h1, l1);
    g_xh[2*i  ] = h0; g_xh[2*i+1] = h1;
    g_xl[2*i  ] = l0; g_xl[2*i+1] = l1;
}

__global__ __launch_bounds__(256) void split_conv_w(
    const float* __restrict__ Wq, const float* __restrict__ Wk,
    const float* __restrict__ Wv, const float* __restrict__ Wo, int nf4)
{
    int i = blockIdx.x*blockDim.x + threadIdx.x;
    if (i >= nf4) return;
    int which = blockIdx.y;
    const float* src = (which==0)?Wq:(which==1)?Wk:(which==2)?Wv:Wo;
    size_t off = (size_t)which*HIDN*XDP;
    float4 v = ((const float4*)src)[i];
    uint32_t h0,l0,h1,l1;
    split_pair(v.x, v.y, h0, l0);
    split_pair(v.z, v.w, h1, l1);
    g_wh[off + 2*i  ] = h0; g_wh[off + 2*i+1] = h1;
    g_wl[off + 2*i  ] = l0; g_wl[off + 2*i+1] = l1;
}

// ---------------------------------------------------------------------------
// Fused QKV projection. grid=(128,12,3), 256 thr. BM=128, BN=64, BK=32dp,
// 2-stage cp.async double buffer, ldmatrix loads (round-14 config).
// z==2 (V): 2-term split; epilogue transposes V in dead stage-0 SMEM and
// writes g_vt[d][keypair] directly (no separate vtrans kernel).
// ---------------------------------------------------------------------------
#define GSTAGE    (128*KS + 128*KS + 64*KS + 64*KS)   // 13824 u32
#define GEMM_SMEM (GSTAGE*2*4)                        // 110592 B
#define GEMM_NK   (XDP/32)                            // 12

__global__ __launch_bounds__(256) void qkv_kernel(
    const float* __restrict__ bq, const float* __restrict__ bk,
    const float* __restrict__ bv,
    const float* __restrict__ cosc, const float* __restrict__ sinc)
{
    extern __shared__ uint32_t smem[];

    const int z    = blockIdx.z;
    const int h    = blockIdx.y;
    const int row0 = blockIdx.x * 128;
    const int tid  = threadIdx.x;
    const int w    = tid >> 5, lane = tid & 31;
    const int g    = lane >> 2, q = lane & 3;
    const int warpm = w >> 1, warpn = w & 1;
    const bool three_term = (z != 2);

    const uint32_t* wbh = g_wh + (size_t)z*HIDN*XDP + (size_t)h*64*XDP;
    const uint32_t* wbl = g_wl + (size_t)z*HIDN*XDP + (size_t)h*64*XDP;
    const float* bias = (z==0) ? bq : (z==1) ? bk : bv;
    uint32_t* ohp = (z==0) ? g_qh : g_kh;
    uint32_t* olp = (z==0) ? g_ql : g_kl;
    const float sc = (z==0) ? 0.125f : 1.0f;

    float c[2][4][4];
    #pragma unroll
    for (int mf=0; mf<2; mf++)
        #pragma unroll
        for (int nf=0; nf<4; nf++)
            #pragma unroll
            for (int e=0; e<4; e++) c[mf][nf][e]=0.f;

    const int lrow = tid >> 3;            // 0..31
    const int koff = (tid & 7) * 4;       // 0..28 u32

    const int rr  = lane & 7;
    const int a_row = rr + ((lane>>3)&1)*8;
    const int a_col = (lane>>4)*4;
    const int b_tt4 = (lane>>3)*4;

    auto load_stage = [&](int it, int st){
        uint32_t* base = smem + st*GSTAGE;
        uint32_t* xh = base;
        uint32_t* xl = base + 128*KS;
        uint32_t* wh = base + 256*KS;
        uint32_t* wl = base + 256*KS + 64*KS;
        int k0 = it*32;
        #pragma unroll
        for (int i=0; i<4; i++){
            int r = lrow + 32*i;
            cp16(smaddr(&xh[r*KS + koff]), g_xh + (size_t)(row0+r)*XDP + k0 + koff);
            if (three_term)
                cp16(smaddr(&xl[r*KS + koff]), g_xl + (size_t)(row0+r)*XDP + k0 + koff);
        }
        #pragma unroll
        for (int i=0; i<2; i++){
            int r = lrow + 32*i;
            cp16(smaddr(&wh[r*KS + koff]), wbh + (size_t)r*XDP + k0 + koff);
            cp16(smaddr(&wl[r*KS + koff]), wbl + (size_t)r*XDP + k0 + koff);
        }
        cp_commit();
    };

    load_stage(0, 0);
    for (int it=0; it<GEMM_NK; it++){
        int cur = it & 1;
        if (it+1 < GEMM_NK) load_stage(it+1, cur^1);
        if (it+1 < GEMM_NK) cp_wait1(); else cp_wait0();
        __syncthreads();
        uint32_t* base = smem + cur*GSTAGE;
        uint32_t* xh = base;
        uint32_t* xl = base + 128*KS;
        uint32_t* wh = base + 256*KS;
        uint32_t* wl = base + 256*KS + 64*KS;
        #pragma unroll
        for (int kfp=0; kfp<2; kfp++){
            uint32_t ah[2][2][4], al[2][2][4];
            #pragma unroll
            for (int kk=0; kk<2; kk++){
                int kf = 2*kfp + kk;
                #pragma unroll
                for (int mf=0; mf<2; mf++){
                    int r = warpm*32 + mf*16 + a_row;
                    ldsm4(ah[kk][mf][0],ah[kk][mf][1],ah[kk][mf][2],ah[kk][mf][3],
                          smaddr(&xh[r*KS + kf*8 + a_col]));
                    if (three_term)
                        ldsm4(al[kk][mf][0],al[kk][mf][1],al[kk][mf][2],al[kk][mf][3],
                              smaddr(&xl[r*KS + kf*8 + a_col]));
                }
            }
            #pragma unroll
            for (int nf=0; nf<4; nf++){
                int n = warpn*32 + nf*8 + rr;
                uint32_t bh0,bh1,bh2,bh3, bl0,bl1,bl2,bl3;
                ldsm4(bh0,bh1,bh2,bh3, smaddr(&wh[n*KS + kfp*16 + b_tt4]));
                ldsm4(bl0,bl1,bl2,bl3, smaddr(&wl[n*KS + kfp*16 + b_tt4]));
                #pragma unroll
                for (int mf=0; mf<2; mf++){
                    mma_f16(c[mf][nf], ah[0][mf][0],ah[0][mf][1],ah[0][mf][2],ah[0][mf][3], bh0,bh1);
                    mma_f16(c[mf][nf], ah[0][mf][0],ah[0][mf][1],ah[0][mf][2],ah[0][mf][3], bl0,bl1);
                    if (three_term)
                        mma_f16(c[mf][nf], al[0][mf][0],al[0][mf][1],al[0][mf][2],al[0][mf][3], bh0,bh1);
                    mma_f16(c[mf][nf], ah[1][mf][0],ah[1][mf][1],ah[1][mf][2],ah[1][mf][3], bh2,bh3);
                    mma_f16(c[mf][nf], ah[1][mf][0],ah[1][mf][1],ah[1][mf][2],ah[1][mf][3], bl2,bl3);
                    if (three_term)
                        mma_f16(c[mf][nf], al[1][mf][0],al[1][mf][1],al[1][mf][2],al[1][mf][3], bh2,bh3);
                }
            }
        }
        __syncthreads();
    }

    if (z != 2){
        // Q/K epilogue: bias + RoPE + scale, split-u32 global stores.
        #pragma unroll
        for (int nf=0; nf<4; nf++){
            int col = warpn*32 + nf*8 + 2*q;
            float b0 = bias[h*64 + col], b1 = bias[h*64 + col + 1];
            int t = col >> 1;
            #pragma unroll
            for (int mf=0; mf<2; mf++){
                #pragma unroll
                for (int half=0; half<2; half++){
                    int row = row0 + warpm*32 + mf*16 + g + half*8;
                    int b_ = row >> 10, s_ = row & 1023;
                    float v0 = c[mf][nf][half*2+0] + b0;
                    float v1 = c[mf][nf][half*2+1] + b1;
                    float cs_ = cosc[s_*32 + t], sn_ = sinc[s_*32 + t];
                    float r0v = (v0*cs_ - v1*sn_)*sc;
                    float r1v = (v1*cs_ + v0*sn_)*sc;
                    uint32_t hi, lo;
                    split_pair(r0v, r1v, hi, lo);
                    size_t idx = ((size_t)(b_*NH + h)*SEQ + s_)*HDP + t;
                    ohp[idx] = hi; olp[idx] = lo;
                }
            }
        }
    } else {
        // V epilogue: bias + split into SMEM vbuf [key][dp] (stage 0 is dead),
        // then byte_perm transpose writing g_vt[d][keypair] directly.
        uint32_t* vbh = smem;                // 128*KS
        uint32_t* vbl = smem + 128*KS;
        #pragma unroll
        for (int nf=0; nf<4; nf++){
            int col = warpn*32 + nf*8 + 2*q;
            float b0 = bias[h*64 + col], b1 = bias[h*64 + col + 1];
            int t = col >> 1;
            #pragma unroll
            for (int mf=0; mf<2; mf++){
                #pragma unroll
                for (int half=0; half<2; half++){
                    int rowl = warpm*32 + mf*16 + g + half*8;   // 0..127
                    float v0 = c[mf][nf][half*2+0] + b0;
                    float v1 = c[mf][nf][half*2+1] + b1;
                    uint32_t hi, lo;
                    split_pair(v0, v1, hi, lo);
                    vbh[rowl*KS + t] = hi;
                    vbl[rowl*KS + t] = lo;
                }
            }
        }
        __syncthreads();

        const int d    = tid & 63;       // 0..63
        const int kgrp = tid >> 6;       // 0..3, 16 keypairs each
        const int dp   = d >> 1;
        const uint32_t sel = (d & 1) ? 0x7632u : 0x5410u;
        const int b_ = row0 >> 10, s0 = row0 & 1023;
        const int bh = b_*NH + h;
        uint32_t outh[16], outl[16];
        #pragma unroll
        for (int j=0; j<16; j++){
            int lk = kgrp*16 + j;        // local keypair 0..63
            outh[j] = __byte_perm(vbh[(2*lk)*KS + dp], vbh[(2*lk+1)*KS + dp], sel);
            outl[j] = __byte_perm(vbl[(2*lk)*KS + dp], vbl[(2*lk+1)*KS + dp], sel);
        }
        uint32_t* dsth = g_vth + ((size_t)bh*HD + d)*(SEQ/2) + s0/2 + kgrp*16;
        uint32_t* dstl = g_vtl + ((size_t)bh*HD + d)*(SEQ/2) + s0/2 + kgrp*16;
        #pragma unroll
        for (int j=0; j<16; j+=4){
            *(uint4*)(dsth + j) = make_uint4(outh[j],outh[j+1],outh[j+2],outh[j+3]);
            *(uint4*)(dstl + j) = make_uint4(outl[j],outl[j+1],outl[j+2],outl[j+3]);
        }
    }
}

// ---------------------------------------------------------------------------
// RSE attention. CTA = 128 query rows of one (b,h), 8 warps. QK^T 3-term;
// PV w_hi-only with w in registers. ldmatrix B-operand loads. (round-14)
// ---------------------------------------------------------------------------
#define KV_STAGE  (4*64*KS)                         // 9216 u32
#define ATTN_SMEM ((KV_STAGE*2)*4)                  // 73728 B

__global__ __launch_bounds__(256) void attn_kernel(const float* __restrict__ lam_p)
{
    extern __shared__ uint32_t smem[];

    const int bh = blockIdx.y;
    const int m0 = blockIdx.x * 128;
    const int tid = threadIdx.x;
    const int w = tid >> 5, lane = tid & 31;
    const int g = lane >> 2, q = lane & 3;
    const float lam = *lam_p;

    uint32_t qah[4][4], qal[4][4];
    {
        const uint32_t* ph = g_qh + ((size_t)bh*SEQ + m0 + 16*w)*HDP;
        const uint32_t* pl = g_ql + ((size_t)bh*SEQ + m0 + 16*w)*HDP;
        #pragma unroll
        for (int kf=0; kf<4; kf++){
            qah[kf][0] = ph[(size_t)(g  )*HDP + kf*8 + q  ];
            qah[kf][1] = ph[(size_t)(g+8)*HDP + kf*8 + q  ];
            qah[kf][2] = ph[(size_t)(g  )*HDP + kf*8 + q+4];
            qah[kf][3] = ph[(size_t)(g+8)*HDP + kf*8 + q+4];
            qal[kf][0] = pl[(size_t)(g  )*HDP + kf*8 + q  ];
            qal[kf][1] = pl[(size_t)(g+8)*HDP + kf*8 + q  ];
            qal[kf][2] = pl[(size_t)(g  )*HDP + kf*8 + q+4];
            qal[kf][3] = pl[(size_t)(g+8)*HDP + kf*8 + q+4];
        }
    }

    float rem0=1.f, rem1=1.f, li0=0.f, li1=0.f, mi0=-INFINITY, mi1=-INFINITY;
    float acc[8][4];
    #pragma unroll
    for (int nf=0; nf<8; nf++)
        #pragma unroll
        for (int e=0; e<4; e++) acc[nf][e]=0.f;

    const float sq0 = (float)(m0 + 16*w + g);
    const float sq1 = sq0 + 8.f;

    const int lrow = tid >> 3;
    const int koff = (tid & 7) * 4;
    const int rr   = lane & 7;
    const int tt4  = (lane >> 3) * 4;

    auto load_tile = [&](int nb2, int st){
        uint32_t* base = smem + st*KV_STAGE;
        uint32_t* kh  = base;
        uint32_t* kl  = base + 64*KS;
        uint32_t* vth = base + 128*KS;
        uint32_t* vtl = base + 192*KS;
        const uint32_t* kph = g_kh + ((size_t)bh*SEQ + nb2*64)*HDP;
        const uint32_t* kpl = g_kl + ((size_t)bh*SEQ + nb2*64)*HDP;
        const uint32_t* vph = g_vth + (size_t)bh*HD*(SEQ/2) + nb2*32;
        const uint32_t* vpl = g_vtl + (size_t)bh*HD*(SEQ/2) + nb2*32;
        #pragma unroll
        for (int i=0; i<2; i++){
            int r = lrow + 32*i;
            cp16(smaddr(&kh[r*KS + koff]),  kph + (size_t)r*HDP + koff);
            cp16(smaddr(&kl[r*KS + koff]),  kpl + (size_t)r*HDP + koff);
            cp16(smaddr(&vth[r*KS + koff]), vph + (size_t)r*(SEQ/2) + koff);
            cp16(smaddr(&vtl[r*KS + koff]), vpl + (size_t)r*(SEQ/2) + koff);
        }
        cp_commit();
    };

    load_tile(0, 0);
    for (int nb2=0; nb2<16; nb2++){
        int cur = nb2 & 1;
        if (nb2+1 < 16) load_tile(nb2+1, cur^1);
        if (nb2+1 < 16) cp_wait1(); else cp_wait0();
        __syncthreads();
        uint32_t* base = smem + cur*KV_STAGE;
        uint32_t* kh  = base;
        uint32_t* kl  = base + 64*KS;
        uint32_t* vth = base + 128*KS;
        uint32_t* vtl = base + 192*KS;

        #pragma unroll
        for (int sub=0; sub<2; sub++){
            const int nb = nb2*2 + sub;

            float cf[4][4];
            #pragma unroll
            for (int nf=0; nf<4; nf++){
                #pragma unroll
                for (int e=0; e<4; e++) cf[nf][e]=0.f;
                int n = sub*32 + nf*8 + rr;
                #pragma unroll
                for (int kfp=0; kfp<2; kfp++){
                    uint32_t bh0,bh1,bh2,bh3, bl0,bl1,bl2,bl3;
                    ldsm4(bh0,bh1,bh2,bh3, smaddr(&kh[n*KS + kfp*16 + tt4]));
                    ldsm4(bl0,bl1,bl2,bl3, smaddr(&kl[n*KS + kfp*16 + tt4]));
                    int kf0 = 2*kfp, kf1 = 2*kfp+1;
                    mma_f16(cf[nf], qah[kf0][0],qah[kf0][1],qah[kf0][2],qah[kf0][3], bh0,bh1);
                    mma_f16(cf[nf], qah[kf0][0],qah[kf0][1],qah[kf0][2],qah[kf0][3], bl0,bl1);
                    mma_f16(cf[nf], qal[kf0][0],qal[kf0][1],qal[kf0][2],qal[kf0][3], bh0,bh1);
                    mma_f16(cf[nf], qah[kf1][0],qah[kf1][1],qah[kf1][2],qah[kf1][3], bh2,bh3);
                    mma_f16(cf[nf], qah[kf1][0],qah[kf1][1],qah[kf1][2],qah[kf1][3], bl2,bl3);
                    mma_f16(cf[nf], qal[kf1][0],qal[kf1][1],qal[kf1][2],qal[kf1][3], bh2,bh3);
                }
            }

            uint32_t wa0[4], wa1[4];
            float sw0=0.f, sw1=0.f, mx0=-INFINITY, mx1=-INFINITY;
            #pragma unroll
            for (int nf=0; nf<4; nf++){
                int colk = nf*8 + 2*q;
                float sk0 = (float)(nb*32 + colk);
                float sk1 = sk0 + 1.f;
                {
                    float raw0 = cf[nf][0] - lam*fabsf(sq0 - sk0);
                    float raw1 = cf[nf][1] - lam*fabsf(sq0 - sk1);
                    mx0 = fmaxf(mx0, fmaxf(raw0, raw1));
                    float cl0 = fminf(fmaxf(raw0, -20.f), 20.f);
                    float cl1 = fminf(fmaxf(raw1, -20.f), 20.f);
                    float w0 = __fdividef(rem0, 1.f + __expf(-cl0));
                    float w1 = __fdividef(rem0, 1.f + __expf(-cl1));
                    sw0 += w0 + w1;
                    wa0[nf] = packh(__float2half_rn(w0), __float2half_rn(w1));
                }
                {
                    float raw0 = cf[nf][2] - lam*fabsf(sq1 - sk0);
                    float raw1 = cf[nf][3] - lam*fabsf(sq1 - sk1);
                    mx1 = fmaxf(mx1, fmaxf(raw0, raw1));
                    float cl0 = fminf(fmaxf(raw0, -20.f), 20.f);
                    float cl1 = fminf(fmaxf(raw1, -20.f), 20.f);
                    float w0 = __fdividef(rem1, 1.f + __expf(-cl0));
                    float w1 = __fdividef(rem1, 1.f + __expf(-cl1));
                    sw1 += w0 + w1;
                    wa1[nf] = packh(__float2half_rn(w0), __float2half_rn(w1));
                }
            }
            #pragma unroll
            for (int ofs=2; ofs>0; ofs>>=1){
                sw0 += __shfl_xor_sync(0xffffffffu, sw0, ofs);
                sw1 += __shfl_xor_sync(0xffffffffu, sw1, ofs);
                mx0  = fmaxf(mx0, __shfl_xor_sync(0xffffffffu, mx0, ofs));
                mx1  = fmaxf(mx1, __shfl_xor_sync(0xffffffffu, mx1, ofs));
            }
            {
                float mn = fmaxf(mi0, mx0);
                li0 = li0*exp2f(mi0-mn) + sw0; mi0 = mn;
                rem0 = fmaxf(rem0*(1.f - sw0), 1e-6f);
            }
            {
                float mn = fmaxf(mi1, mx1);
                li1 = li1*exp2f(mi1-mn) + sw1; mi1 = mn;
                rem1 = fmaxf(rem1*(1.f - sw1), 1e-6f);
            }

            #pragma unroll
            for (int nf=0; nf<8; nf++){
                int n = nf*8 + rr;
                uint32_t vh0,vh1,vh2,vh3, vl0,vl1,vl2,vl3;
                ldsm4(vh0,vh1,vh2,vh3, smaddr(&vth[n*KS + sub*16 + tt4]));
                ldsm4(vl0,vl1,vl2,vl3, smaddr(&vtl[n*KS + sub*16 + tt4]));
                mma_f16(acc[nf], wa0[0],wa1[0],wa0[1],wa1[1], vh0,vh1);
                mma_f16(acc[nf], wa0[0],wa1[0],wa0[1],wa1[1], vl0,vl1);
                mma_f16(acc[nf], wa0[2],wa1[2],wa0[3],wa1[3], vh2,vh3);
                mma_f16(acc[nf], wa0[2],wa1[2],wa0[3],wa1[3], vl2,vl3);
            }
        }
        __syncthreads();
    }

    const float inv0 = __fdividef(1.f, fmaxf(li0, 1e-6f));
    const float inv1 = __fdividef(1.f, fmaxf(li1, 1e-6f));
    uint32_t* poh = g_oh + ((size_t)bh*SEQ + m0 + 16*w)*HDP;
    #pragma unroll
    for (int nf=0; nf<8; nf++){
        int dp = nf*4 + q;
        poh[(size_t)(g  )*HDP + dp] =
            packh(__float2half_rn(acc[nf][0]*inv0), __float2half_rn(acc[nf][1]*inv0));
        poh[(size_t)(g+8)*HDP + dp] =
            packh(__float2half_rn(acc[nf][2]*inv1), __float2half_rn(acc[nf][3]*inv1));
    }
}

// ---------------------------------------------------------------------------
// Output projection: y = O_hi @ (Wo_hi + Wo_lo)^T + bo. grid=(128,12).
// BM=128, BN=64, BK=32dp, 2-stage cp.async, ldmatrix fragment loads.
// ---------------------------------------------------------------------------
#define OSTAGE   (128*KS + 64*KS + 64*KS)   // 9216 u32
#define OUT_SMEM (OSTAGE*2*4)               // 73728 B

__global__ __launch_bounds__(256) void out_kernel(
    const float* __restrict__ bo, float* __restrict__ y)
{
    extern __shared__ uint32_t smem[];

    const int row0 = blockIdx.x * 128;
    const int cb   = blockIdx.y;
    const int tid  = threadIdx.x;
    const int w    = tid >> 5, lane = tid & 31;
    const int g    = lane >> 2, q = lane & 3;
    const int warpm = w >> 1, warpn = w & 1;

    float c[2][4][4];
    #pragma unroll
    for (int mf=0; mf<2; mf++)
        #pragma unroll
        for (int nf=0; nf<4; nf++)
            #pragma unroll
            for (int e=0; e<4; e++) c[mf][nf][e]=0.f;

    const int lrow = tid >> 3;
    const int koff = (tid & 7) * 4;
    const int rr  = lane & 7;
    const int a_row = rr + ((lane>>3)&1)*8;
    const int a_col = (lane>>4)*4;
    const int b_tt4 = (lane>>3)*4;
    const uint32_t* wbh = g_wh + (size_t)(3*HIDN + cb*64)*XDP;
    const uint32_t* wbl = g_wl + (size_t)(3*HIDN + cb*64)*XDP;

    auto load_stage = [&](int it, int st){
        uint32_t* base = smem + st*OSTAGE;
        uint32_t* xh = base;
        uint32_t* wh = base + 128*KS;
        uint32_t* wl = base + 128*KS + 64*KS;
        int k0 = it*32;
        const int hh = it;               // BK = one head
        #pragma unroll
        for (int i=0; i<4; i++){
            int r = lrow + 32*i;
            int grow = row0 + r;
            int b_ = grow >> 10, s_ = grow & 1023;
            size_t xi = ((size_t)(b_*NH + hh)*SEQ + s_)*HDP + koff;
            cp16(smaddr(&xh[r*KS + koff]), g_oh + xi);
        }
        #pragma unroll
        for (int i=0; i<2; i++){
            int r = lrow + 32*i;
            cp16(smaddr(&wh[r*KS + koff]), wbh + (size_t)r*XDP + k0 + koff);
            cp16(smaddr(&wl[r*KS + koff]), wbl + (size_t)r*XDP + k0 + koff);
        }
        cp_commit();
    };

    load_stage(0, 0);
    for (int it=0; it<GEMM_NK; it++){
        int cur = it & 1;
        if (it+1 < GEMM_NK) load_stage(it+1, cur^1);
        if (it+1 < GEMM_NK) cp_wait1(); else cp_wait0();
        __syncthreads();
        uint32_t* base = smem + cur*OSTAGE;
        uint32_t* xh = base;
        uint32_t* wh = base + 128*KS;
        uint32_t* wl = base + 128*KS + 64*KS;
        #pragma unroll
        for (int kfp=0; kfp<2; kfp++){
            uint32_t ah[2][2][4];
            #pragma unroll
            for (int kk=0; kk<2; kk++){
                int kf = 2*kfp + kk;
                #pragma unroll
                for (int mf=0; mf<2; mf++){
                    int r = warpm*32 + mf*16 + a_row;
                    ldsm4(ah[kk][mf][0],ah[kk][mf][1],ah[kk][mf][2],ah[kk][mf][3],
                          smaddr(&xh[r*KS + kf*8 + a_col]));
                }
            }
            #pragma unroll
            for (int nf=0; nf<4; nf++){
                int n = warpn*32 + nf*8 + rr;
                uint32_t bh0,bh1,bh2,bh3, bl0,bl1,bl2,bl3;
                ldsm4(bh0,bh1,bh2,bh3, smaddr(&wh[n*KS + kfp*16 + b_tt4]));
                ldsm4(bl0,bl1,bl2,bl3, smaddr(&wl[n*KS + kfp*16 + b_tt4]));
                #pragma unroll
                for (int mf=0; mf<2; mf++){
                    mma_f16(c[mf][nf], ah[0][mf][0],ah[0][mf][1],ah[0][mf][2],ah[0][mf][3], bh0,bh1);
                    mma_f16(c[mf][nf], ah[0][mf][0],ah[0][mf][1],ah[0][mf][2],ah[0][mf][3], bl0,bl1);
                    mma_f16(c[mf][nf], ah[1][mf][0],ah[1][mf][1],ah[1][mf][2],ah[1][mf][3], bh2,bh3);
                    mma_f16(c[mf][nf], ah[1][mf][0],ah[1][mf][1],ah[1][mf][2],ah[1][mf][3], bl2,bl3);
                }
            }
        }
        __syncthreads();
    }

    #pragma unroll
    for (int nf=0; nf<4; nf++){
        int col = cb*64 + warpn*32 + nf*8 + 2*q;
        float b0 = bo[col], b1 = bo[col+1];
        #pragma unroll
        for (int mf=0; mf<2; mf++){
            #pragma unroll
            for (int half=0; half<2; half++){
                int row = row0 + warpm*32 + mf*16 + g + half*8;
                *(float2*)(y + (size_t)row*HIDN + col) =
                    make_float2(c[mf][nf][half*2+0] + b0,
                                c[mf][nf][half*2+1] + b1);
            }
        }
    }
}

// ---------------------------------------------------------------------------
extern "C" void kernel_launch(void* const* d_in, const int* in_sizes, int n_in,
                              void* d_out, int out_size)
{
    const float* x    = (const float*)d_in[0];
    const float* Wq   = (const float*)d_in[1];
    const float* bq   = (const float*)d_in[2];
    const float* Wk   = (const float*)d_in[3];
    const float* bk   = (const float*)d_in[4];
    const float* Wv   = (const float*)d_in[5];
    const float* bv   = (const float*)d_in[6];
    const float* Wo   = (const float*)d_in[7];
    const float* bo   = (const float*)d_in[8];
    const float* lam  = (const float*)d_in[9];
    const float* cosc = (const float*)d_in[10];
    const float* sinc = (const float*)d_in[11];
    float* y = (float*)d_out;

    static int configured = 0;
    if (!configured){
        cudaFuncSetAttribute(qkv_kernel,  cudaFuncAttributeMaxDynamicSharedMemorySize, GEMM_SMEM);
        cudaFuncSetAttribute(attn_kernel, cudaFuncAttributeMaxDynamicSharedMemorySize, ATTN_SMEM);
        cudaFuncSetAttribute(out_kernel,  cudaFuncAttributeMaxDynamicSharedMemorySize, OUT_SMEM);
        configured = 1;
    }

    const int nf4_x = BDIM*SEQ*HIDN/4;
    const int nf4_w = HIDN*HIDN/4;
    split_conv_x<<<(nf4_x+255)/256, 256>>>(x, nf4_x);
    dim3 gw((nf4_w+255)/256, 4);
    split_conv_w<<<gw, 256>>>(Wq, Wk, Wv, Wo, nf4_w);

    dim3 g1(BDIM*SEQ/128, NH, 3);
    qkv_kernel<<<g1, 256, GEMM_SMEM>>>(bq, bk, bv, cosc, sinc);

    dim3 g2(SEQ/128, NBH);
    attn_kernel<<<g2, 256, ATTN_SMEM>>>(lam);

    dim3 g3(BDIM*SEQ/128, NH);
    out_kernel<<<g3, 256, OUT_SMEM>>>(bo, y);
}

// round 17
// speedup vs baseline: 1.1880x; 1.0811x over previous
#include <cuda_runtime.h>
#include <cuda_fp16.h>
#include <math.h>
#include <stdint.h>

#define BDIM 16
#define SEQ  1024
#define HIDN 768
#define NH   12
#define HD   64
#define NBH  (BDIM*NH)   // 192
#define XDP  384          // dpairs per hidden row
#define HDP  32           // dpairs per head row

// Split-fp16 scratch (u32 = half2). Allocation-free: __device__ globals.
__device__ uint32_t g_xh[(size_t)BDIM*SEQ*XDP], g_xl[(size_t)BDIM*SEQ*XDP];
__device__ uint32_t g_wh[(size_t)4*HIDN*XDP],   g_wl[(size_t)4*HIDN*XDP];
__device__ uint32_t g_qh[(size_t)NBH*SEQ*HDP],  g_ql[(size_t)NBH*SEQ*HDP];
__device__ uint32_t g_kh[(size_t)NBH*SEQ*HDP],  g_kl[(size_t)NBH*SEQ*HDP];
__device__ uint32_t g_vth[(size_t)NBH*HD*(SEQ/2)], g_vtl[(size_t)NBH*HD*(SEQ/2)];
__device__ uint32_t g_oh[(size_t)NBH*SEQ*HDP];   // O stored fp16-hi only

__device__ __forceinline__ void mma_f16(float c[4],
    uint32_t a0, uint32_t a1, uint32_t a2, uint32_t a3,
    uint32_t b0, uint32_t b1)
{
    asm volatile(
        "mma.sync.aligned.m16n8k16.row.col.f32.f16.f16.f32 "
        "{%0,%1,%2,%3},{%4,%5,%6,%7},{%8,%9},{%0,%1,%2,%3};\n"
        : "+f"(c[0]), "+f"(c[1]), "+f"(c[2]), "+f"(c[3])
        : "r"(a0), "r"(a1), "r"(a2), "r"(a3), "r"(b0), "r"(b1));
}

__device__ __forceinline__ void ldsm4(uint32_t &r0, uint32_t &r1,
                                      uint32_t &r2, uint32_t &r3, uint32_t a){
    asm volatile("ldmatrix.sync.aligned.m8n8.x4.shared.b16 {%0,%1,%2,%3}, [%4];"
        : "=r"(r0), "=r"(r1), "=r"(r2), "=r"(r3) : "r"(a));
}

__device__ __forceinline__ uint32_t packh(__half a, __half b){
    __half2 h = __halves2half2(a, b);
    return *(uint32_t*)&h;
}
__device__ __forceinline__ void split_pair(float x, float y, uint32_t &hi, uint32_t &lo){
    __half hx = __float2half_rn(x);
    __half hy = __float2half_rn(y);
    __half lx = __float2half_rn(x - __half2float(hx));
    __half ly = __float2half_rn(y - __half2float(hy));
    hi = packh(hx, hy);
    lo = packh(lx, ly);
}

__device__ __forceinline__ uint32_t smaddr(const void* p){
    return (uint32_t)__cvta_generic_to_shared(p);
}
__device__ __forceinline__ void cp16(uint32_t s, const void* g){
    asm volatile("cp.async.cg.shared.global [%0], [%1], 16;\n" :: "r"(s), "l"(g));
}
__device__ __forceinline__ void cp_commit(){
    asm volatile("cp.async.commit_group;\n" ::: "memory");
}
__device__ __forceinline__ void cp_wait1(){
    asm volatile("cp.async.wait_group 1;\n" ::: "memory");
}
__device__ __forceinline__ void cp_wait0(){
    asm volatile("cp.async.wait_group 0;\n" ::: "memory");
}

#define KS 36   // stride for 32-dpair rows; (4r+c)%32 bank permutation

// ---------------------------------------------------------------------------
// Split conversions.
// ---------------------------------------------------------------------------
__global__ __launch_bounds__(256) void split_conv_x(const float* __restrict__ src,
                                                    int nf4)
{
    int i = blockIdx.x*blockDim.x + threadIdx.x;
    if (i >= nf4) return;
    float4 v = ((const float4*)src)[i];
    uint32_t h0,l0,h1,l1;
    split_pair(v.x, v.y, h0, l0);
    split_pair(v.z, v.w, h1, l1);
    g_xh[2*i  ] = h0; g_xh[2*i+1] = h1;
    g_xl[2*i  ] = l0; g_xl[2*i+1] = l1;
}

__global__ __launch_bounds__(256) void split_conv_w(
    const float* __restrict__ Wq, const float* __restrict__ Wk,
    const float* __restrict__ Wv, const float* __restrict__ Wo, int nf4)
{
    int i = blockIdx.x*blockDim.x + threadIdx.x;
    if (i >= nf4) return;
    int which = blockIdx.y;
    const float* src = (which==0)?Wq:(which==1)?Wk:(which==2)?Wv:Wo;
    size_t off = (size_t)which*HIDN*XDP;
    float4 v = ((const float4*)src)[i];
    uint32_t h0,l0,h1,l1;
    split_pair(v.x, v.y, h0, l0);
    split_pair(v.z, v.w, h1, l1);
    g_wh[off + 2*i  ] = h0; g_wh[off + 2*i+1] = h1;
    g_wl[off + 2*i  ] = l0; g_wl[off + 2*i+1] = l1;
}

// ---------------------------------------------------------------------------
// Fused QKV projection. grid=(128,12,3), 256 thr. BM=128, BN=64, BK=32dp,
// 2-stage cp.async double buffer, ldmatrix loads. z==2 (V): 2-term split;
// epilogue transposes V in dead stage-0 SMEM, writes g_vt directly.
// ---------------------------------------------------------------------------
#define GSTAGE    (128*KS + 128*KS + 64*KS + 64*KS)   // 13824 u32
#define GEMM_SMEM (GSTAGE*2*4)                        // 110592 B
#define GEMM_NK   (XDP/32)                            // 12

__global__ __launch_bounds__(256) void qkv_kernel(
    const float* __restrict__ bq, const float* __restrict__ bk,
    const float* __restrict__ bv,
    const float* __restrict__ cosc, const float* __restrict__ sinc)
{
    extern __shared__ uint32_t smem[];

    const int z    = blockIdx.z;
    const int h    = blockIdx.y;
    const int row0 = blockIdx.x * 128;
    const int tid  = threadIdx.x;
    const int w    = tid >> 5, lane = tid & 31;
    const int g    = lane >> 2, q = lane & 3;
    const int warpm = w >> 1, warpn = w & 1;
    const bool three_term = (z != 2);

    const uint32_t* wbh = g_wh + (size_t)z*HIDN*XDP + (size_t)h*64*XDP;
    const uint32_t* wbl = g_wl + (size_t)z*HIDN*XDP + (size_t)h*64*XDP;
    const float* bias = (z==0) ? bq : (z==1) ? bk : bv;
    uint32_t* ohp = (z==0) ? g_qh : g_kh;
    uint32_t* olp = (z==0) ? g_ql : g_kl;
    const float sc = (z==0) ? 0.125f : 1.0f;

    float c[2][4][4];
    #pragma unroll
    for (int mf=0; mf<2; mf++)
        #pragma unroll
        for (int nf=0; nf<4; nf++)
            #pragma unroll
            for (int e=0; e<4; e++) c[mf][nf][e]=0.f;

    const int lrow = tid >> 3;            // 0..31
    const int koff = (tid & 7) * 4;       // 0..28 u32

    const int rr  = lane & 7;
    const int a_row = rr + ((lane>>3)&1)*8;
    const int a_col = (lane>>4)*4;
    const int b_tt4 = (lane>>3)*4;

    auto load_stage = [&](int it, int st){
        uint32_t* base = smem + st*GSTAGE;
        uint32_t* xh = base;
        uint32_t* xl = base + 128*KS;
        uint32_t* wh = base + 256*KS;
        uint32_t* wl = base + 256*KS + 64*KS;
        int k0 = it*32;
        #pragma unroll
        for (int i=0; i<4; i++){
            int r = lrow + 32*i;
            cp16(smaddr(&xh[r*KS + koff]), g_xh + (size_t)(row0+r)*XDP + k0 + koff);
            if (three_term)
                cp16(smaddr(&xl[r*KS + koff]), g_xl + (size_t)(row0+r)*XDP + k0 + koff);
        }
        #pragma unroll
        for (int i=0; i<2; i++){
            int r = lrow + 32*i;
            cp16(smaddr(&wh[r*KS + koff]), wbh + (size_t)r*XDP + k0 + koff);
            cp16(smaddr(&wl[r*KS + koff]), wbl + (size_t)r*XDP + k0 + koff);
        }
        cp_commit();
    };

    load_stage(0, 0);
    for (int it=0; it<GEMM_NK; it++){
        int cur = it & 1;
        if (it+1 < GEMM_NK) load_stage(it+1, cur^1);
        if (it+1 < GEMM_NK) cp_wait1(); else cp_wait0();
        __syncthreads();
        uint32_t* base = smem + cur*GSTAGE;
        uint32_t* xh = base;
        uint32_t* xl = base + 128*KS;
        uint32_t* wh = base + 256*KS;
        uint32_t* wl = base + 256*KS + 64*KS;
        #pragma unroll
        for (int kfp=0; kfp<2; kfp++){
            uint32_t ah[2][2][4], al[2][2][4];
            #pragma unroll
            for (int kk=0; kk<2; kk++){
                int kf = 2*kfp + kk;
                #pragma unroll
                for (int mf=0; mf<2; mf++){
                    int r = warpm*32 + mf*16 + a_row;
                    ldsm4(ah[kk][mf][0],ah[kk][mf][1],ah[kk][mf][2],ah[kk][mf][3],
                          smaddr(&xh[r*KS + kf*8 + a_col]));
                    if (three_term)
                        ldsm4(al[kk][mf][0],al[kk][mf][1],al[kk][mf][2],al[kk][mf][3],
                              smaddr(&xl[r*KS + kf*8 + a_col]));
                }
            }
            #pragma unroll
            for (int nf=0; nf<4; nf++){
                int n = warpn*32 + nf*8 + rr;
                uint32_t bh0,bh1,bh2,bh3, bl0,bl1,bl2,bl3;
                ldsm4(bh0,bh1,bh2,bh3, smaddr(&wh[n*KS + kfp*16 + b_tt4]));
                ldsm4(bl0,bl1,bl2,bl3, smaddr(&wl[n*KS + kfp*16 + b_tt4]));
                #pragma unroll
                for (int mf=0; mf<2; mf++){
                    mma_f16(c[mf][nf], ah[0][mf][0],ah[0][mf][1],ah[0][mf][2],ah[0][mf][3], bh0,bh1);
                    mma_f16(c[mf][nf], ah[0][mf][0],ah[0][mf][1],ah[0][mf][2],ah[0][mf][3], bl0,bl1);
                    if (three_term)
                        mma_f16(c[mf][nf], al[0][mf][0],al[0][mf][1],al[0][mf][2],al[0][mf][3], bh0,bh1);
                    mma_f16(c[mf][nf], ah[1][mf][0],ah[1][mf][1],ah[1][mf][2],ah[1][mf][3], bh2,bh3);
                    mma_f16(c[mf][nf], ah[1][mf][0],ah[1][mf][1],ah[1][mf][2],ah[1][mf][3], bl2,bl3);
                    if (three_term)
                        mma_f16(c[mf][nf], al[1][mf][0],al[1][mf][1],al[1][mf][2],al[1][mf][3], bh2,bh3);
                }
            }
        }
        __syncthreads();
    }

    if (z != 2){
        // Q/K epilogue: bias + RoPE + scale, split-u32 global stores.
        #pragma unroll
        for (int nf=0; nf<4; nf++){
            int col = warpn*32 + nf*8 + 2*q;
            float b0 = bias[h*64 + col], b1 = bias[h*64 + col + 1];
            int t = col >> 1;
            #pragma unroll
            for (int mf=0; mf<2; mf++){
                #pragma unroll
                for (int half=0; half<2; half++){
                    int row = row0 + warpm*32 + mf*16 + g + half*8;
                    int b_ = row >> 10, s_ = row & 1023;
                    float v0 = c[mf][nf][half*2+0] + b0;
                    float v1 = c[mf][nf][half*2+1] + b1;
                    float cs_ = cosc[s_*32 + t], sn_ = sinc[s_*32 + t];
                    float r0v = (v0*cs_ - v1*sn_)*sc;
                    float r1v = (v1*cs_ + v0*sn_)*sc;
                    uint32_t hi, lo;
                    split_pair(r0v, r1v, hi, lo);
                    size_t idx = ((size_t)(b_*NH + h)*SEQ + s_)*HDP + t;
                    ohp[idx] = hi; olp[idx] = lo;
                }
            }
        }
    } else {
        // V epilogue: bias + split into SMEM vbuf [key][dp] (stage 0 is dead),
        // then byte_perm transpose writing g_vt[d][keypair] directly.
        uint32_t* vbh = smem;                // 128*KS
        uint32_t* vbl = smem + 128*KS;
        #pragma unroll
        for (int nf=0; nf<4; nf++){
            int col = warpn*32 + nf*8 + 2*q;
            float b0 = bias[h*64 + col], b1 = bias[h*64 + col + 1];
            int t = col >> 1;
            #pragma unroll
            for (int mf=0; mf<2; mf++){
                #pragma unroll
                for (int half=0; half<2; half++){
                    int rowl = warpm*32 + mf*16 + g + half*8;   // 0..127
                    float v0 = c[mf][nf][half*2+0] + b0;
                    float v1 = c[mf][nf][half*2+1] + b1;
                    uint32_t hi, lo;
                    split_pair(v0, v1, hi, lo);
                    vbh[rowl*KS + t] = hi;
                    vbl[rowl*KS + t] = lo;
                }
            }
        }
        __syncthreads();

        const int d    = tid & 63;       // 0..63
        const int kgrp = tid >> 6;       // 0..3, 16 keypairs each
        const int dp   = d >> 1;
        const uint32_t sel = (d & 1) ? 0x7632u : 0x5410u;
        const int b_ = row0 >> 10, s0 = row0 & 1023;
        const int bh = b_*NH + h;
        uint32_t outh[16], outl[16];
        #pragma unroll
        for (int j=0; j<16; j++){
            int lk = kgrp*16 + j;        // local keypair 0..63
            outh[j] = __byte_perm(vbh[(2*lk)*KS + dp], vbh[(2*lk+1)*KS + dp], sel);
            outl[j] = __byte_perm(vbl[(2*lk)*KS + dp], vbl[(2*lk+1)*KS + dp], sel);
        }
        uint32_t* dsth = g_vth + ((size_t)bh*HD + d)*(SEQ/2) + s0/2 + kgrp*16;
        uint32_t* dstl = g_vtl + ((size_t)bh*HD + d)*(SEQ/2) + s0/2 + kgrp*16;
        #pragma unroll
        for (int j=0; j<16; j+=4){
            *(uint4*)(dsth + j) = make_uint4(outh[j],outh[j+1],outh[j+2],outh[j+3]);
            *(uint4*)(dstl + j) = make_uint4(outl[j],outl[j+1],outl[j+2],outl[j+3]);
        }
    }
}

// ---------------------------------------------------------------------------
// RSE attention. CTA = 128 query rows of one (b,h), 8 warps. QK^T 3-term;
// PV w_hi-only with w in registers. ldmatrix B-operand loads.
// __launch_bounds__(256, 2): force <=128 regs so 2 CTAs/SM fit.
// ---------------------------------------------------------------------------
#define KV_STAGE  (4*64*KS)                         // 9216 u32
#define ATTN_SMEM ((KV_STAGE*2)*4)                  // 73728 B

__global__ __launch_bounds__(256, 2) void attn_kernel(const float* __restrict__ lam_p)
{
    extern __shared__ uint32_t smem[];

    const int bh = blockIdx.y;
    const int m0 = blockIdx.x * 128;
    const int tid = threadIdx.x;
    const int w = tid >> 5, lane = tid & 31;
    const int g = lane >> 2, q = lane & 3;
    const float lam = *lam_p;

    uint32_t qah[4][4], qal[4][4];
    {
        const uint32_t* ph = g_qh + ((size_t)bh*SEQ + m0 + 16*w)*HDP;
        const uint32_t* pl = g_ql + ((size_t)bh*SEQ + m0 + 16*w)*HDP;
        #pragma unroll
        for (int kf=0; kf<4; kf++){
            qah[kf][0] = ph[(size_t)(g  )*HDP + kf*8 + q  ];
            qah[kf][1] = ph[(size_t)(g+8)*HDP + kf*8 + q  ];
            qah[kf][2] = ph[(size_t)(g  )*HDP + kf*8 + q+4];
            qah[kf][3] = ph[(size_t)(g+8)*HDP + kf*8 + q+4];
            qal[kf][0] = pl[(size_t)(g  )*HDP + kf*8 + q  ];
            qal[kf][1] = pl[(size_t)(g+8)*HDP + kf*8 + q  ];
            qal[kf][2] = pl[(size_t)(g  )*HDP + kf*8 + q+4];
            qal[kf][3] = pl[(size_t)(g+8)*HDP + kf*8 + q+4];
        }
    }

    float rem0=1.f, rem1=1.f, li0=0.f, li1=0.f, mi0=-INFINITY, mi1=-INFINITY;
    float acc[8][4];
    #pragma unroll
    for (int nf=0; nf<8; nf++)
        #pragma unroll
        for (int e=0; e<4; e++) acc[nf][e]=0.f;

    const float sq0 = (float)(m0 + 16*w + g);
    const float sq1 = sq0 + 8.f;

    const int lrow = tid >> 3;
    const int koff = (tid & 7) * 4;
    const int rr   = lane & 7;
    const int tt4  = (lane >> 3) * 4;

    auto load_tile = [&](int nb2, int st){
        uint32_t* base = smem + st*KV_STAGE;
        uint32_t* kh  = base;
        uint32_t* kl  = base + 64*KS;
        uint32_t* vth = base + 128*KS;
        uint32_t* vtl = base + 192*KS;
        const uint32_t* kph = g_kh + ((size_t)bh*SEQ + nb2*64)*HDP;
        const uint32_t* kpl = g_kl + ((size_t)bh*SEQ + nb2*64)*HDP;
        const uint32_t* vph = g_vth + (size_t)bh*HD*(SEQ/2) + nb2*32;
        const uint32_t* vpl = g_vtl + (size_t)bh*HD*(SEQ/2) + nb2*32;
        #pragma unroll
        for (int i=0; i<2; i++){
            int r = lrow + 32*i;
            cp16(smaddr(&kh[r*KS + koff]),  kph + (size_t)r*HDP + koff);
            cp16(smaddr(&kl[r*KS + koff]),  kpl + (size_t)r*HDP + koff);
            cp16(smaddr(&vth[r*KS + koff]), vph + (size_t)r*(SEQ/2) + koff);
            cp16(smaddr(&vtl[r*KS + koff]), vpl + (size_t)r*(SEQ/2) + koff);
        }
        cp_commit();
    };

    load_tile(0, 0);
    for (int nb2=0; nb2<16; nb2++){
        int cur = nb2 & 1;
        if (nb2+1 < 16) load_tile(nb2+1, cur^1);
        if (nb2+1 < 16) cp_wait1(); else cp_wait0();
        __syncthreads();
        uint32_t* base = smem + cur*KV_STAGE;
        uint32_t* kh  = base;
        uint32_t* kl  = base + 64*KS;
        uint32_t* vth = base + 128*KS;
        uint32_t* vtl = base + 192*KS;

        #pragma unroll
        for (int sub=0; sub<2; sub++){
            const int nb = nb2*2 + sub;

            float cf[4][4];
            #pragma unroll
            for (int nf=0; nf<4; nf++){
                #pragma unroll
                for (int e=0; e<4; e++) cf[nf][e]=0.f;
                int n = sub*32 + nf*8 + rr;
                #pragma unroll
                for (int kfp=0; kfp<2; kfp++){
                    uint32_t bh0,bh1,bh2,bh3, bl0,bl1,bl2,bl3;
                    ldsm4(bh0,bh1,bh2,bh3, smaddr(&kh[n*KS + kfp*16 + tt4]));
                    ldsm4(bl0,bl1,bl2,bl3, smaddr(&kl[n*KS + kfp*16 + tt4]));
                    int kf0 = 2*kfp, kf1 = 2*kfp+1;
                    mma_f16(cf[nf], qah[kf0][0],qah[kf0][1],qah[kf0][2],qah[kf0][3], bh0,bh1);
                    mma_f16(cf[nf], qah[kf0][0],qah[kf0][1],qah[kf0][2],qah[kf0][3], bl0,bl1);
                    mma_f16(cf[nf], qal[kf0][0],qal[kf0][1],qal[kf0][2],qal[kf0][3], bh0,bh1);
                    mma_f16(cf[nf], qah[kf1][0],qah[kf1][1],qah[kf1][2],qah[kf1][3], bh2,bh3);
                    mma_f16(cf[nf], qah[kf1][0],qah[kf1][1],qah[kf1][2],qah[kf1][3], bl2,bl3);
                    mma_f16(cf[nf], qal[kf1][0],qal[kf1][1],qal[kf1][2],qal[kf1][3], bh2,bh3);
                }
            }

            uint32_t wa0[4], wa1[4];
            float sw0=0.f, sw1=0.f, mx0=-INFINITY, mx1=-INFINITY;
            #pragma unroll
            for (int nf=0; nf<4; nf++){
                int colk = nf*8 + 2*q;
                float sk0 = (float)(nb*32 + colk);
                float sk1 = sk0 + 1.f;
                {
                    float raw0 = cf[nf][0] - lam*fabsf(sq0 - sk0);
                    float raw1 = cf[nf][1] - lam*fabsf(sq0 - sk1);
                    mx0 = fmaxf(mx0, fmaxf(raw0, raw1));
                    float cl0 = fminf(fmaxf(raw0, -20.f), 20.f);
                    float cl1 = fminf(fmaxf(raw1, -20.f), 20.f);
                    float w0 = __fdividef(rem0, 1.f + __expf(-cl0));
                    float w1 = __fdividef(rem0, 1.f + __expf(-cl1));
                    sw0 += w0 + w1;
                    wa0[nf] = packh(__float2half_rn(w0), __float2half_rn(w1));
                }
                {
                    float raw0 = cf[nf][2] - lam*fabsf(sq1 - sk0);
                    float raw1 = cf[nf][3] - lam*fabsf(sq1 - sk1);
                    mx1 = fmaxf(mx1, fmaxf(raw0, raw1));
                    float cl0 = fminf(fmaxf(raw0, -20.f), 20.f);
                    float cl1 = fminf(fmaxf(raw1, -20.f), 20.f);
                    float w0 = __fdividef(rem1, 1.f + __expf(-cl0));
                    float w1 = __fdividef(rem1, 1.f + __expf(-cl1));
                    sw1 += w0 + w1;
                    wa1[nf] = packh(__float2half_rn(w0), __float2half_rn(w1));
                }
            }
            #pragma unroll
            for (int ofs=2; ofs>0; ofs>>=1){
                sw0 += __shfl_xor_sync(0xffffffffu, sw0, ofs);
                sw1 += __shfl_xor_sync(0xffffffffu, sw1, ofs);
                mx0  = fmaxf(mx0, __shfl_xor_sync(0xffffffffu, mx0, ofs));
                mx1  = fmaxf(mx1, __shfl_xor_sync(0xffffffffu, mx1, ofs));
            }
            {
                float mn = fmaxf(mi0, mx0);
                li0 = li0*exp2f(mi0-mn) + sw0; mi0 = mn;
                rem0 = fmaxf(rem0*(1.f - sw0), 1e-6f);
            }
            {
                float mn = fmaxf(mi1, mx1);
                li1 = li1*exp2f(mi1-mn) + sw1; mi1 = mn;
                rem1 = fmaxf(rem1*(1.f - sw1), 1e-6f);
            }

            #pragma unroll
            for (int nf=0; nf<8; nf++){
                int n = nf*8 + rr;
                uint32_t vh0,vh1,vh2,vh3, vl0,vl1,vl2,vl3;
                ldsm4(vh0,vh1,vh2,vh3, smaddr(&vth[n*KS + sub*16 + tt4]));
                ldsm4(vl0,vl1,vl2,vl3, smaddr(&vtl[n*KS + sub*16 + tt4]));
                mma_f16(acc[nf], wa0[0],wa1[0],wa0[1],wa1[1], vh0,vh1);
                mma_f16(acc[nf], wa0[0],wa1[0],wa0[1],wa1[1], vl0,vl1);
                mma_f16(acc[nf], wa0[2],wa1[2],wa0[3],wa1[3], vh2,vh3);
                mma_f16(acc[nf], wa0[2],wa1[2],wa0[3],wa1[3], vl2,vl3);
            }
        }
        __syncthreads();
    }

    const float inv0 = __fdividef(1.f, fmaxf(li0, 1e-6f));
    const float inv1 = __fdividef(1.f, fmaxf(li1, 1e-6f));
    uint32_t* poh = g_oh + ((size_t)bh*SEQ + m0 + 16*w)*HDP;
    #pragma unroll
    for (int nf=0; nf<8; nf++){
        int dp = nf*4 + q;
        poh[(size_t)(g  )*HDP + dp] =
            packh(__float2half_rn(acc[nf][0]*inv0), __float2half_rn(acc[nf][1]*inv0));
        poh[(size_t)(g+8)*HDP + dp] =
            packh(__float2half_rn(acc[nf][2]*inv1), __float2half_rn(acc[nf][3]*inv1));
    }
}

// ---------------------------------------------------------------------------
// Output projection: y = O_hi @ (Wo_hi + Wo_lo)^T + bo. grid=(128,12).
// BM=128, BN=64, BK=32dp, 2-stage cp.async, ldmatrix fragment loads.
// ---------------------------------------------------------------------------
#define OSTAGE   (128*KS + 64*KS + 64*KS)   // 9216 u32
#define OUT_SMEM (OSTAGE*2*4)               // 73728 B

__global__ __launch_bounds__(256) void out_kernel(
    const float* __restrict__ bo, float* __restrict__ y)
{
    extern __shared__ uint32_t smem[];

    const int row0 = blockIdx.x * 128;
    const int cb   = blockIdx.y;
    const int tid  = threadIdx.x;
    const int w    = tid >> 5, lane = tid & 31;
    const int g    = lane >> 2, q = lane & 3;
    const int warpm = w >> 1, warpn = w & 1;

    float c[2][4][4];
    #pragma unroll
    for (int mf=0; mf<2; mf++)
        #pragma unroll
        for (int nf=0; nf<4; nf++)
            #pragma unroll
            for (int e=0; e<4; e++) c[mf][nf][e]=0.f;

    const int lrow = tid >> 3;
    const int koff = (tid & 7) * 4;
    const int rr  = lane & 7;
    const int a_row = rr + ((lane>>3)&1)*8;
    const int a_col = (lane>>4)*4;
    const int b_tt4 = (lane>>3)*4;
    const uint32_t* wbh = g_wh + (size_t)(3*HIDN + cb*64)*XDP;
    const uint32_t* wbl = g_wl + (size_t)(3*HIDN + cb*64)*XDP;

    auto load_stage = [&](int it, int st){
        uint32_t* base = smem + st*OSTAGE;
        uint32_t* xh = base;
        uint32_t* wh = base + 128*KS;
        uint32_t* wl = base + 128*KS + 64*KS;
        int k0 = it*32;
        const int hh = it;               // BK = one head
        #pragma unroll
        for (int i=0; i<4; i++){
            int r = lrow + 32*i;
            int grow = row0 + r;
            int b_ = grow >> 10, s_ = grow & 1023;
            size_t xi = ((size_t)(b_*NH + hh)*SEQ + s_)*HDP + koff;
            cp16(smaddr(&xh[r*KS + koff]), g_oh + xi);
        }
        #pragma unroll
        for (int i=0; i<2; i++){
            int r = lrow + 32*i;
            cp16(smaddr(&wh[r*KS + koff]), wbh + (size_t)r*XDP + k0 + koff);
            cp16(smaddr(&wl[r*KS + koff]), wbl + (size_t)r*XDP + k0 + koff);
        }
        cp_commit();
    };

    load_stage(0, 0);
    for (int it=0; it<GEMM_NK; it++){
        int cur = it & 1;
        if (it+1 < GEMM_NK) load_stage(it+1, cur^1);
        if (it+1 < GEMM_NK) cp_wait1(); else cp_wait0();
        __syncthreads();
        uint32_t* base = smem + cur*OSTAGE;
        uint32_t* xh = base;
        uint32_t* wh = base + 128*KS;
        uint32_t* wl = base + 128*KS + 64*KS;
        #pragma unroll
        for (int kfp=0; kfp<2; kfp++){
            uint32_t ah[2][2][4];
            #pragma unroll
            for (int kk=0; kk<2; kk++){
                int kf = 2*kfp + kk;
                #pragma unroll
                for (int mf=0; mf<2; mf++){
                    int r = warpm*32 + mf*16 + a_row;
                    ldsm4(ah[kk][mf][0],ah[kk][mf][1],ah[kk][mf][2],ah[kk][mf][3],
                          smaddr(&xh[r*KS + kf*8 + a_col]));
                }
            }
            #pragma unroll
            for (int nf=0; nf<4; nf++){
                int n = warpn*32 + nf*8 + rr;
                uint32_t bh0,bh1,bh2,bh3, bl0,bl1,bl2,bl3;
                ldsm4(bh0,bh1,bh2,bh3, smaddr(&wh[n*KS + kfp*16 + b_tt4]));
                ldsm4(bl0,bl1,bl2,bl3, smaddr(&wl[n*KS + kfp*16 + b_tt4]));
                #pragma unroll
                for (int mf=0; mf<2; mf++){
                    mma_f16(c[mf][nf], ah[0][mf][0],ah[0][mf][1],ah[0][mf][2],ah[0][mf][3], bh0,bh1);
                    mma_f16(c[mf][nf], ah[0][mf][0],ah[0][mf][1],ah[0][mf][2],ah[0][mf][3], bl0,bl1);
                    mma_f16(c[mf][nf], ah[1][mf][0],ah[1][mf][1],ah[1][mf][2],ah[1][mf][3], bh2,bh3);
                    mma_f16(c[mf][nf], ah[1][mf][0],ah[1][mf][1],ah[1][mf][2],ah[1][mf][3], bl2,bl3);
                }
            }
        }
        __syncthreads();
    }

    #pragma unroll
    for (int nf=0; nf<4; nf++){
        int col = cb*64 + warpn*32 + nf*8 + 2*q;
        float b0 = bo[col], b1 = bo[col+1];
        #pragma unroll
        for (int mf=0; mf<2; mf++){
            #pragma unroll
            for (int half=0; half<2; half++){
                int row = row0 + warpm*32 + mf*16 + g + half*8;
                *(float2*)(y + (size_t)row*HIDN + col) =
                    make_float2(c[mf][nf][half*2+0] + b0,
                                c[mf][nf][half*2+1] + b1);
            }
        }
    }
}

// ---------------------------------------------------------------------------
extern "C" void kernel_launch(void* const* d_in, const int* in_sizes, int n_in,
                              void* d_out, int out_size)
{
    const float* x    = (const float*)d_in[0];
    const float* Wq   = (const float*)d_in[1];
    const float* bq   = (const float*)d_in[2];
    const float* Wk   = (const float*)d_in[3];
    const float* bk   = (const float*)d_in[4];
    const float* Wv   = (const float*)d_in[5];
    const float* bv   = (const float*)d_in[6];
    const float* Wo   = (const float*)d_in[7];
    const float* bo   = (const float*)d_in[8];
    const float* lam  = (const float*)d_in[9];
    const float* cosc = (const float*)d_in[10];
    const float* sinc = (const float*)d_in[11];
    float* y = (float*)d_out;

    static int configured = 0;
    if (!configured){
        cudaFuncSetAttribute(qkv_kernel,  cudaFuncAttributeMaxDynamicSharedMemorySize, GEMM_SMEM);
        cudaFuncSetAttribute(attn_kernel, cudaFuncAttributeMaxDynamicSharedMemorySize, ATTN_SMEM);
        cudaFuncSetAttribute(out_kernel,  cudaFuncAttributeMaxDynamicSharedMemorySize, OUT_SMEM);
        configured = 1;
    }

    const int nf4_x = BDIM*SEQ*HIDN/4;
    const int nf4_w = HIDN*HIDN/4;
    split_conv_x<<<(nf4_x+255)/256, 256>>>(x, nf4_x);
    dim3 gw((nf4_w+255)/256, 4);
    split_conv_w<<<gw, 256>>>(Wq, Wk, Wv, Wo, nf4_w);

    dim3 g1(BDIM*SEQ/128, NH, 3);
    qkv_kernel<<<g1, 256, GEMM_SMEM>>>(bq, bk, bv, cosc, sinc);

    dim3 g2(SEQ/128, NBH);
    attn_kernel<<<g2, 256, ATTN_SMEM>>>(lam);

    dim3 g3(BDIM*SEQ/128, NH);
    out_kernel<<<g3, 256, OUT_SMEM>>>(bo, y);
}